// round 2
// baseline (speedup 1.0000x reference)
#include <cuda_runtime.h>
#include <cstdint>

#define NN  100000
#define RR  3
#define EE  320000
#define HH  4
#define HD_ 128
#define NNR (RR * NN)

// ---------------- scratch (device globals; no allocs allowed) ----------------
__device__ float    g_hs  [(size_t)RR * NN * HD_];   // hs per relation  [r][n][128]
__device__ float    g_rst [(size_t)RR * NN * HD_];   // z_r
__device__ float    g_el  [NNR * HH];
__device__ float    g_er  [NNR * HH];
__device__ float    g_A   [RR * 128 * 128];          // Wt_src[r] @ Wg[r]
__device__ float    g_csrc[RR * 128];                // bt_src[r] @ Wg[r]
__device__ float    g_erw [RR * 128 * HH];           // combined er weights [r][f][h]
__device__ float    g_erb [RR * HH];
__device__ float    g_wsum[RR];
__device__ float    g_aw  [RR];
// CSR build
__device__ int      g_deg [NNR];
__device__ int      g_off [NNR];
__device__ int      g_cur [NNR];
__device__ int      g_bsum[512];
__device__ int      g_boff[512];
__device__ int      g_csr [RR * EE];

// ---------------- weight combination ----------------
__global__ void k_combine_src(const float* __restrict__ Wt_src,
                              const float* __restrict__ bt_src,
                              const float* __restrict__ Wg) {
    int r = blockIdx.y, f = blockIdx.x, j = threadIdx.x;
    __shared__ float wt[128];
    wt[j] = Wt_src[(r * 128 + f) * 128 + j];
    __syncthreads();
    const float* wg = Wg + r * 128 * 128;
    float acc = 0.f;
#pragma unroll 8
    for (int i = 0; i < 128; i++) acc += wt[i] * wg[i * 128 + j];
    g_A[(r * 128 + f) * 128 + j] = acc;
    if (f == 0) {
        float c = 0.f;
        for (int i = 0; i < 128; i++) c += bt_src[r * 128 + i] * wg[i * 128 + j];
        g_csrc[r * 128 + j] = c;
    }
}

__global__ void k_combine_dst(const float* __restrict__ Wt_dst,
                              const float* __restrict__ bt_dst,
                              const float* __restrict__ Wg,
                              const float* __restrict__ attn_r) {
    int r = blockIdx.x, t = threadIdx.x;  // 128 threads
    __shared__ float P[128][4];
    const float* wg = Wg + r * 128 * 128;
    const float* ar = attn_r + r * 128;
    for (int h = 0; h < 4; h++) {
        float s = 0.f;
        for (int d = 0; d < 32; d++) s += wg[t * 128 + h * 32 + d] * ar[h * 32 + d];
        P[t][h] = s;
    }
    __syncthreads();
    float s[4] = {0.f, 0.f, 0.f, 0.f};
    for (int i = 0; i < 128; i++) {
        float w = Wt_dst[t * 128 + i];
        for (int h = 0; h < 4; h++) s[h] += w * P[i][h];
    }
    for (int h = 0; h < 4; h++) g_erw[(r * 128 + t) * 4 + h] = s[h];
    if (t < 4) {
        float b = 0.f;
        for (int i = 0; i < 128; i++) b += bt_dst[i] * P[i][t];
        g_erb[r * 4 + t] = b;
    }
}

// er[r][n][h] = dst_feat[n] . er_w[r][:,h] + er_b[r][h]
__global__ void k_er(const float* __restrict__ dst_feat) {
    __shared__ float sw[RR * 128 * 4];
    __shared__ float sb[RR * 4];
    int t = threadIdx.x;
    for (int idx = t; idx < RR * 128 * 4; idx += blockDim.x) sw[idx] = g_erw[idx];
    if (t < RR * 4) sb[t] = g_erb[t];
    __syncthreads();
    int n = blockIdx.x * blockDim.x + t;
    if (n >= NN) return;
    float acc[RR * 4];
    for (int q = 0; q < RR * 4; q++) acc[q] = sb[q];
    const float4* row = (const float4*)(dst_feat + (size_t)n * 128);
#pragma unroll 4
    for (int f4 = 0; f4 < 32; f4++) {
        float4 v = row[f4];
        const float c[4] = {v.x, v.y, v.z, v.w};
        for (int cc = 0; cc < 4; cc++) {
            int f = f4 * 4 + cc;
            for (int r = 0; r < RR; r++)
                for (int h = 0; h < 4; h++)
                    acc[r * 4 + h] += c[cc] * sw[(r * 128 + f) * 4 + h];
        }
    }
    for (int r = 0; r < RR; r++)
        for (int h = 0; h < 4; h++)
            g_er[(r * NN + n) * 4 + h] = acc[r * 4 + h];
}

// ---------------- hs GEMM: [N,128] @ [128,128] + bias, fused el epilogue ----------------
__global__ __launch_bounds__(256) void k_hs(const float* __restrict__ src_feats,
                                            const float* __restrict__ attn_l) {
    int r = blockIdx.y;
    int row0 = blockIdx.x * 32;
    __shared__ float Wsh[64][128];
    __shared__ float Ash[32][64];
    __shared__ float elbuf[32][4][8];
    __shared__ float alsh[128];
    __shared__ float csh[128];
    int t = threadIdx.x;
    if (t < 128) { alsh[t] = attn_l[r * 128 + t]; csh[t] = g_csrc[r * 128 + t]; }
    const float* A = g_A + r * 128 * 128;
    const float* X = src_feats + (size_t)r * NN * 128;
    float acc[4][4];
    for (int i = 0; i < 4; i++) for (int c = 0; c < 4; c++) acc[i][c] = 0.f;
    int rg = t >> 5, cg = t & 31;
    int colb = cg * 4;
    for (int kc = 0; kc < 128; kc += 64) {
        __syncthreads();
        // W: 64x128 floats = 2048 float4, 8 per thread
        for (int idx = t; idx < 2048; idx += 256) {
            int kk = idx >> 5, j4 = idx & 31;
            *(float4*)&Wsh[kk][j4 * 4] = *(const float4*)&A[(kc + kk) * 128 + j4 * 4];
        }
        // A: 32x64 floats = 512 float4, 2 per thread
        for (int idx = t; idx < 512; idx += 256) {
            int rr = idx >> 4, c4 = idx & 15;
            *(float4*)&Ash[rr][c4 * 4] = *(const float4*)&X[(size_t)(row0 + rr) * 128 + kc + c4 * 4];
        }
        __syncthreads();
#pragma unroll
        for (int k4 = 0; k4 < 64; k4 += 4) {
            float4 w0 = *(const float4*)&Wsh[k4 + 0][colb];
            float4 w1 = *(const float4*)&Wsh[k4 + 1][colb];
            float4 w2 = *(const float4*)&Wsh[k4 + 2][colb];
            float4 w3 = *(const float4*)&Wsh[k4 + 3][colb];
#pragma unroll
            for (int i = 0; i < 4; i++) {
                float4 a = *(const float4*)&Ash[rg * 4 + i][k4];
                acc[i][0] += a.x * w0.x + a.y * w1.x + a.z * w2.x + a.w * w3.x;
                acc[i][1] += a.x * w0.y + a.y * w1.y + a.z * w2.y + a.w * w3.y;
                acc[i][2] += a.x * w0.z + a.y * w1.z + a.z * w2.z + a.w * w3.z;
                acc[i][3] += a.x * w0.w + a.y * w1.w + a.z * w2.w + a.w * w3.w;
            }
        }
    }
    float* hsout = g_hs + ((size_t)r * NN + row0) * 128;
#pragma unroll
    for (int i = 0; i < 4; i++) {
        int row = rg * 4 + i;
        float4 v;
        v.x = acc[i][0] + csh[colb + 0];
        v.y = acc[i][1] + csh[colb + 1];
        v.z = acc[i][2] + csh[colb + 2];
        v.w = acc[i][3] + csh[colb + 3];
        float elp = v.x * alsh[colb] + v.y * alsh[colb + 1] + v.z * alsh[colb + 2] + v.w * alsh[colb + 3];
        *(float4*)(hsout + (size_t)row * 128 + colb) = v;
        elbuf[row][cg >> 3][cg & 7] = elp;
    }
    __syncthreads();
    if (t < 128) {
        int row = t >> 2, h = t & 3;
        float s = 0.f;
        for (int q = 0; q < 8; q++) s += elbuf[row][h][q];
        g_el[((size_t)r * NN + row0 + row) * 4 + h] = s;
    }
}

// ---------------- CSR build ----------------
__global__ void k_hist(const int* __restrict__ dst_idx) {
    int r = blockIdx.y;
    int e = blockIdx.x * blockDim.x + threadIdx.x;
    if (e >= EE) return;
    atomicAdd(&g_deg[r * NN + dst_idx[r * EE + e]], 1);
}

__global__ void k_scan1() {
    __shared__ int wsum[32];
    int i = blockIdx.x * 1024 + threadIdx.x;
    int lane = threadIdx.x & 31, wid = threadIdx.x >> 5;
    int v = (i < NNR) ? g_deg[i] : 0;
    int x = v;
#pragma unroll
    for (int o = 1; o < 32; o <<= 1) {
        int y = __shfl_up_sync(0xffffffffu, x, o);
        if (lane >= o) x += y;
    }
    if (lane == 31) wsum[wid] = x;
    __syncthreads();
    if (wid == 0) {
        int s = wsum[lane];
        int t2 = s;
#pragma unroll
        for (int o = 1; o < 32; o <<= 1) {
            int y = __shfl_up_sync(0xffffffffu, t2, o);
            if (lane >= o) t2 += y;
        }
        wsum[lane] = t2 - s;
        if (lane == 31) g_bsum[blockIdx.x] = t2;
    }
    __syncthreads();
    if (i < NNR) g_off[i] = x - v + wsum[wid];
}

__global__ void k_scan2(int nblocks) {
    __shared__ int wsum[32];
    int i = threadIdx.x;
    int lane = i & 31, wid = i >> 5;
    int v = (i < nblocks) ? g_bsum[i] : 0;
    int x = v;
#pragma unroll
    for (int o = 1; o < 32; o <<= 1) {
        int y = __shfl_up_sync(0xffffffffu, x, o);
        if (lane >= o) x += y;
    }
    if (lane == 31) wsum[wid] = x;
    __syncthreads();
    if (wid == 0) {
        int s = wsum[lane];
        int t2 = s;
#pragma unroll
        for (int o = 1; o < 32; o <<= 1) {
            int y = __shfl_up_sync(0xffffffffu, t2, o);
            if (lane >= o) t2 += y;
        }
        wsum[lane] = t2 - s;
    }
    __syncthreads();
    if (i < nblocks) g_boff[i] = x - v + wsum[wid];
}

__global__ void k_scan3() {
    int i = blockIdx.x * 1024 + threadIdx.x;
    if (i < NNR) g_off[i] += g_boff[blockIdx.x];
}

__global__ void k_scatter(const int* __restrict__ src_idx, const int* __restrict__ dst_idx) {
    int r = blockIdx.y;
    int e = blockIdx.x * blockDim.x + threadIdx.x;
    if (e >= EE) return;
    int idx = r * NN + dst_idx[r * EE + e];
    int pos = g_off[idx] + atomicAdd(&g_cur[idx], 1);
    g_csr[pos] = src_idx[r * EE + e];
}

// ---------------- fused: edge softmax + aggregate + bias + ELU ----------------
// one warp per (r, n); softmax without max-shift (mathematically identical)
__global__ __launch_bounds__(256) void k_agg(const float* __restrict__ bias_g) {
    int warp = (blockIdx.x * blockDim.x + threadIdx.x) >> 5;
    if (warp >= NNR) return;
    int lane = threadIdx.x & 31;
    int r = warp / NN;
    float4 er4 = *(const float4*)&g_er[warp * 4];
    int start = g_off[warp];
    int deg = g_deg[warp];
    const float* hsbase = g_hs + (size_t)r * NN * 128;
    float ss0 = 0.f, ss1 = 0.f, ss2 = 0.f, ss3 = 0.f;
    float a0 = 0.f, a1 = 0.f, a2 = 0.f, a3 = 0.f;
    for (int j = 0; j < deg; j++) {
        int s = g_csr[start + j];
        float4 el4 = *(const float4*)&g_el[(r * NN + s) * 4];
        float e0 = el4.x + er4.x; e0 = e0 > 0.f ? e0 : 0.2f * e0;
        float e1 = el4.y + er4.y; e1 = e1 > 0.f ? e1 : 0.2f * e1;
        float e2 = el4.z + er4.z; e2 = e2 > 0.f ? e2 : 0.2f * e2;
        float e3 = el4.w + er4.w; e3 = e3 > 0.f ? e3 : 0.2f * e3;
        float x0 = __expf(e0), x1 = __expf(e1), x2 = __expf(e2), x3 = __expf(e3);
        ss0 += x0; ss1 += x1; ss2 += x2; ss3 += x3;
        const float* hp = hsbase + (size_t)s * 128 + lane;
        a0 += x0 * hp[0];
        a1 += x1 * hp[32];
        a2 += x2 * hp[64];
        a3 += x3 * hp[96];
    }
    float i0 = 1.f / (ss0 + 1e-9f);
    float i1 = 1.f / (ss1 + 1e-9f);
    float i2 = 1.f / (ss2 + 1e-9f);
    float i3 = 1.f / (ss3 + 1e-9f);
    const float* bg = bias_g + r * 128 + lane;
    float v0 = a0 * i0 + bg[0];
    float v1 = a1 * i1 + bg[32];
    float v2 = a2 * i2 + bg[64];
    float v3 = a3 * i3 + bg[96];
    v0 = v0 > 0.f ? v0 : expm1f(v0);
    v1 = v1 > 0.f ? v1 : expm1f(v1);
    v2 = v2 > 0.f ? v2 : expm1f(v2);
    v3 = v3 > 0.f ? v3 : expm1f(v3);
    float* zp = g_rst + (size_t)warp * 128 + lane;
    zp[0] = v0; zp[32] = v1; zp[64] = v2; zp[96] = v3;
}

// ---------------- semantic attention GEMM: w-sum per relation ----------------
__global__ __launch_bounds__(256) void k_sem(const float* __restrict__ W1,
                                             const float* __restrict__ b1,
                                             const float* __restrict__ W2) {
    int row0 = blockIdx.x * 32;  // rows over flattened [R*N]
    __shared__ float Wsh[64][128];
    __shared__ float Ash[32][64];
    __shared__ float b1sh[128];
    __shared__ float w2sh[128];
    __shared__ float wsums[8];
    int t = threadIdx.x;
    if (t < 128) { b1sh[t] = b1[t]; w2sh[t] = W2[t]; }
    float acc[4][4];
    for (int i = 0; i < 4; i++) for (int c = 0; c < 4; c++) acc[i][c] = 0.f;
    int rg = t >> 5, cg = t & 31;
    int colb = cg * 4;
    for (int kc = 0; kc < 128; kc += 64) {
        __syncthreads();
        for (int idx = t; idx < 2048; idx += 256) {
            int kk = idx >> 5, j4 = idx & 31;
            *(float4*)&Wsh[kk][j4 * 4] = *(const float4*)&W1[(kc + kk) * 128 + j4 * 4];
        }
        for (int idx = t; idx < 512; idx += 256) {
            int rr = idx >> 4, c4 = idx & 15;
            *(float4*)&Ash[rr][c4 * 4] = *(const float4*)&g_rst[(size_t)(row0 + rr) * 128 + kc + c4 * 4];
        }
        __syncthreads();
#pragma unroll
        for (int k4 = 0; k4 < 64; k4 += 4) {
            float4 w0 = *(const float4*)&Wsh[k4 + 0][colb];
            float4 w1 = *(const float4*)&Wsh[k4 + 1][colb];
            float4 w2 = *(const float4*)&Wsh[k4 + 2][colb];
            float4 w3 = *(const float4*)&Wsh[k4 + 3][colb];
#pragma unroll
            for (int i = 0; i < 4; i++) {
                float4 a = *(const float4*)&Ash[rg * 4 + i][k4];
                acc[i][0] += a.x * w0.x + a.y * w1.x + a.z * w2.x + a.w * w3.x;
                acc[i][1] += a.x * w0.y + a.y * w1.y + a.z * w2.y + a.w * w3.y;
                acc[i][2] += a.x * w0.z + a.y * w1.z + a.z * w2.z + a.w * w3.z;
                acc[i][3] += a.x * w0.w + a.y * w1.w + a.z * w2.w + a.w * w3.w;
            }
        }
    }
    float tot = 0.f;
#pragma unroll
    for (int i = 0; i < 4; i++) {
        float p = 0.f;
        for (int c = 0; c < 4; c++)
            p += w2sh[colb + c] * tanhf(acc[i][c] + b1sh[colb + c]);
        tot += p;
    }
    for (int off = 16; off; off >>= 1) tot += __shfl_down_sync(0xffffffffu, tot, off);
    if (cg == 0) wsums[rg] = tot;
    __syncthreads();
    if (t == 0) {
        float s = 0.f;
        for (int q = 0; q < 8; q++) s += wsums[q];
        int r = row0 / NN;
        atomicAdd(&g_wsum[r], s);
    }
}

// ---------------- softmax over relations ----------------
__global__ void k_soft(float* __restrict__ out, int out_size) {
    if (threadIdx.x == 0) {
        float w[RR];
        float m = -1e30f;
        for (int r = 0; r < RR; r++) { w[r] = g_wsum[r] / (float)NN; m = fmaxf(m, w[r]); }
        float s = 0.f;
        for (int r = 0; r < RR; r++) { w[r] = expf(w[r] - m); s += w[r]; }
        for (int r = 0; r < RR; r++) {
            float a = w[r] / s;
            g_aw[r] = a;
            out[out_size - RR + r] = a;
        }
    }
}

// ---------------- final weighted combination ----------------
__global__ void k_out(float* __restrict__ out) {
    int t = blockIdx.x * blockDim.x + threadIdx.x;
    if (t >= NN * 32) return;
    float a0 = g_aw[0], a1 = g_aw[1], a2 = g_aw[2];
    const float4* z0 = (const float4*)g_rst + t;
    const float4* z1 = z0 + (size_t)NN * 32;
    const float4* z2 = z1 + (size_t)NN * 32;
    float4 x = *z0, y = *z1, z = *z2;
    float4 o;
    o.x = a0 * x.x + a1 * y.x + a2 * z.x;
    o.y = a0 * x.y + a1 * y.y + a2 * z.y;
    o.z = a0 * x.z + a1 * y.z + a2 * z.z;
    o.w = a0 * x.w + a1 * y.w + a2 * z.w;
    ((float4*)out)[t] = o;
}

// ---------------- launch ----------------
extern "C" void kernel_launch(void* const* d_in, const int* in_sizes, int n_in,
                              void* d_out, int out_size) {
    const float* dst_feat  = (const float*)d_in[0];
    const float* src_feats = (const float*)d_in[1];
    const int*   src_idx   = (const int*)d_in[2];
    const int*   dst_idx   = (const int*)d_in[3];
    const float* Wt_dst    = (const float*)d_in[4];
    const float* bt_dst    = (const float*)d_in[5];
    const float* Wt_src    = (const float*)d_in[6];
    const float* bt_src    = (const float*)d_in[7];
    const float* Wg        = (const float*)d_in[8];
    const float* attn_l    = (const float*)d_in[9];
    const float* attn_r    = (const float*)d_in[10];
    const float* bias_g    = (const float*)d_in[11];
    const float* W1        = (const float*)d_in[12];
    const float* b1        = (const float*)d_in[13];
    const float* W2        = (const float*)d_in[14];
    float* out = (float*)d_out;

    void *pd, *pc, *pw;
    cudaGetSymbolAddress(&pd, g_deg);
    cudaGetSymbolAddress(&pc, g_cur);
    cudaGetSymbolAddress(&pw, g_wsum);
    cudaMemsetAsync(pd, 0, NNR * 4, 0);
    cudaMemsetAsync(pc, 0, NNR * 4, 0);
    cudaMemsetAsync(pw, 0, RR * 4, 0);

    const int SCAN_BLOCKS = (NNR + 1023) / 1024;  // 293

    k_combine_src<<<dim3(128, RR), 128>>>(Wt_src, bt_src, Wg);
    k_combine_dst<<<RR, 128>>>(Wt_dst, bt_dst, Wg, attn_r);
    k_er<<<(NN + 127) / 128, 128>>>(dst_feat);
    k_hist<<<dim3((EE + 255) / 256, RR), 256>>>(dst_idx);
    k_scan1<<<SCAN_BLOCKS, 1024>>>();
    k_scan2<<<1, 1024>>>(SCAN_BLOCKS);
    k_scan3<<<SCAN_BLOCKS, 1024>>>();
    k_scatter<<<dim3((EE + 255) / 256, RR), 256>>>(src_idx, dst_idx);
    k_hs<<<dim3(NN / 32, RR), 256>>>(src_feats, attn_l);
    k_agg<<<(NNR * 32 + 255) / 256, 256>>>(bias_g);
    k_sem<<<NNR / 32, 256>>>(W1, b1, W2);
    k_soft<<<1, 32>>>(out, out_size);
    k_out<<<(NN * 32 + 255) / 256, 256>>>(out);
}

// round 3
// speedup vs baseline: 1.4687x; 1.4687x over previous
#include <cuda_runtime.h>
#include <cstdint>

#define NN  100000
#define RR  3
#define EE  320000
#define HH  4
#define HD_ 128
#define NNR (RR * NN)

// ---------------- scratch (device globals; no allocs allowed) ----------------
__device__ float    g_hs  [(size_t)RR * NN * HD_];   // hs per relation  [r][n][128]
__device__ float    g_rst [(size_t)RR * NN * HD_];   // z_r
__device__ float    g_el  [NNR * HH];
__device__ float    g_er  [NNR * HH];
__device__ unsigned g_Ap  [RR * 128 * 128];          // Wt_src@Wg, tf32, fragment-permuted
__device__ unsigned g_W1p [128 * 128];               // W1, tf32, fragment-permuted
__device__ float    g_csrc[RR * 128];                // bt_src[r] @ Wg[r]
__device__ float    g_erw [RR * 128 * HH];
__device__ float    g_erb [RR * HH];
__device__ float    g_wsum[RR];
__device__ float    g_aw  [RR];
// CSR build
__device__ int      g_deg [NNR];
__device__ int      g_off [NNR];
__device__ int      g_cur [NNR];
__device__ int      g_bsum[512];
__device__ int      g_boff[512];
__device__ int      g_csr [RR * EE];

// fragment-permute position for B operand of m16n8k8.row.col (k x n element)
__host__ __device__ __forceinline__ int bpos(int k, int n) {
    int s = k >> 3, kl = k & 7, slot = kl >> 2, tig = kl & 3;
    int jt = n >> 3, g = n & 7;
    return ((s * 16 + jt) * 32 + g * 4 + tig) * 2 + slot;
}

__device__ __forceinline__ unsigned tf32r(float f) {
    unsigned v;
    asm("cvt.rna.tf32.f32 %0, %1;" : "=r"(v) : "f"(f));
    return v;
}

__device__ __forceinline__ void mma_tf32(float c[4], unsigned a0, unsigned a1,
                                         unsigned a2, unsigned a3,
                                         unsigned b0, unsigned b1) {
    asm volatile(
        "mma.sync.aligned.m16n8k8.row.col.f32.tf32.tf32.f32 "
        "{%0,%1,%2,%3},{%4,%5,%6,%7},{%8,%9},{%0,%1,%2,%3};"
        : "+f"(c[0]), "+f"(c[1]), "+f"(c[2]), "+f"(c[3])
        : "r"(a0), "r"(a1), "r"(a2), "r"(a3), "r"(b0), "r"(b1));
}

// ---------------- weight combination (writes permuted tf32 B) ----------------
__global__ void k_combine_src(const float* __restrict__ Wt_src,
                              const float* __restrict__ bt_src,
                              const float* __restrict__ Wg) {
    int r = blockIdx.y, f = blockIdx.x, j = threadIdx.x;
    __shared__ float wt[128];
    wt[j] = Wt_src[(r * 128 + f) * 128 + j];
    __syncthreads();
    const float* wg = Wg + r * 128 * 128;
    float acc = 0.f;
#pragma unroll 8
    for (int i = 0; i < 128; i++) acc += wt[i] * wg[i * 128 + j];
    g_Ap[r * 16384 + bpos(f, j)] = tf32r(acc);
    if (f == 0) {
        float c = 0.f;
        for (int i = 0; i < 128; i++) c += bt_src[r * 128 + i] * wg[i * 128 + j];
        g_csrc[r * 128 + j] = c;
    }
}

__global__ void k_permW1(const float* __restrict__ W1) {
    int k = blockIdx.x, j = threadIdx.x;
    g_W1p[bpos(k, j)] = tf32r(W1[k * 128 + j]);
}

__global__ void k_combine_dst(const float* __restrict__ Wt_dst,
                              const float* __restrict__ bt_dst,
                              const float* __restrict__ Wg,
                              const float* __restrict__ attn_r) {
    int r = blockIdx.x, t = threadIdx.x;  // 128 threads
    __shared__ float P[128][4];
    const float* wg = Wg + r * 128 * 128;
    const float* ar = attn_r + r * 128;
    for (int h = 0; h < 4; h++) {
        float s = 0.f;
        for (int d = 0; d < 32; d++) s += wg[t * 128 + h * 32 + d] * ar[h * 32 + d];
        P[t][h] = s;
    }
    __syncthreads();
    float s[4] = {0.f, 0.f, 0.f, 0.f};
    for (int i = 0; i < 128; i++) {
        float w = Wt_dst[t * 128 + i];
        for (int h = 0; h < 4; h++) s[h] += w * P[i][h];
    }
    for (int h = 0; h < 4; h++) g_erw[(r * 128 + t) * 4 + h] = s[h];
    if (t < 4) {
        float b = 0.f;
        for (int i = 0; i < 128; i++) b += bt_dst[i] * P[i][t];
        g_erb[r * 4 + t] = b;
    }
}

// er[r][n][h] = dst_feat[n] . er_w[r][:,h] + er_b[r][h]
__global__ void k_er(const float* __restrict__ dst_feat) {
    __shared__ float sw[RR * 128 * 4];
    __shared__ float sb[RR * 4];
    int t = threadIdx.x;
    for (int idx = t; idx < RR * 128 * 4; idx += blockDim.x) sw[idx] = g_erw[idx];
    if (t < RR * 4) sb[t] = g_erb[t];
    __syncthreads();
    int n = blockIdx.x * blockDim.x + t;
    if (n >= NN) return;
    float acc[RR * 4];
    for (int q = 0; q < RR * 4; q++) acc[q] = sb[q];
    const float4* row = (const float4*)(dst_feat + (size_t)n * 128);
#pragma unroll 4
    for (int f4 = 0; f4 < 32; f4++) {
        float4 v = row[f4];
        const float c[4] = {v.x, v.y, v.z, v.w};
        for (int cc = 0; cc < 4; cc++) {
            int f = f4 * 4 + cc;
            for (int r = 0; r < RR; r++)
                for (int h = 0; h < 4; h++)
                    acc[r * 4 + h] += c[cc] * sw[(r * 128 + f) * 4 + h];
        }
    }
    for (int r = 0; r < RR; r++)
        for (int h = 0; h < 4; h++)
            g_er[(r * NN + n) * 4 + h] = acc[r * 4 + h];
}

// ---------------- hs GEMM on tensor cores, fused el epilogue ----------------
// block: 128 thr (4 warps); tile 64 rows x 128 cols; K=128
__global__ __launch_bounds__(128) void k_hs_tc(const float* __restrict__ src_feats,
                                               const float* __restrict__ attn_l) {
    extern __shared__ float sm[];
    float* Xs = sm;                               // 64 x 132
    unsigned* Wp = (unsigned*)(sm + 64 * 132);    // 16384
    float* csh = sm + 64 * 132 + 16384;           // 128
    float* alsh = csh + 128;                      // 128
    int r = blockIdx.y;
    int row0 = blockIdx.x * 64;
    int t = threadIdx.x;

    const uint4* Asrc = (const uint4*)(g_Ap + r * 16384);
    uint4* Wd = (uint4*)Wp;
    for (int i = t; i < 4096; i += 128) Wd[i] = Asrc[i];
    csh[t] = g_csrc[r * 128 + t];
    alsh[t] = attn_l[r * 128 + t];
    const float* X = src_feats + (size_t)r * NN * 128;
    for (int i = t; i < 2048; i += 128) {
        int rr = i >> 5, c4 = i & 31;
        float4 v = make_float4(0.f, 0.f, 0.f, 0.f);
        if (row0 + rr < NN) v = *(const float4*)&X[(size_t)(row0 + rr) * 128 + c4 * 4];
        *(float4*)&Xs[rr * 132 + c4 * 4] = v;
    }
    __syncthreads();

    int warp = t >> 5, lane = t & 31, g = lane >> 2, tig = lane & 3;
    int wr = warp * 16;
    float c[16][4];
#pragma unroll
    for (int j = 0; j < 16; j++)
        for (int q = 0; q < 4; q++) c[j][q] = 0.f;

#pragma unroll
    for (int s = 0; s < 16; s++) {
        int k0 = s * 8;
        unsigned a0 = __float_as_uint(Xs[(wr + g) * 132 + k0 + tig]);
        unsigned a1 = __float_as_uint(Xs[(wr + g + 8) * 132 + k0 + tig]);
        unsigned a2 = __float_as_uint(Xs[(wr + g) * 132 + k0 + tig + 4]);
        unsigned a3 = __float_as_uint(Xs[(wr + g + 8) * 132 + k0 + tig + 4]);
#pragma unroll
        for (int jt = 0; jt < 16; jt++) {
            uint2 b = *(const uint2*)&Wp[((s * 16 + jt) * 32 + lane) * 2];
            mma_tf32(c[jt], a0, a1, a2, a3, b.x, b.y);
        }
    }

    // epilogue: +csrc bias, write hs, fused el
    int rowa = row0 + wr + g;
    int rowb = rowa + 8;
    float* hsout = g_hs + (size_t)r * NN * 128;
    float el0[4] = {0.f, 0.f, 0.f, 0.f};
    float el1[4] = {0.f, 0.f, 0.f, 0.f};
#pragma unroll
    for (int jt = 0; jt < 16; jt++) {
        int col = jt * 8 + tig * 2;
        float v0 = c[jt][0] + csh[col], v1 = c[jt][1] + csh[col + 1];
        float v2 = c[jt][2] + csh[col], v3 = c[jt][3] + csh[col + 1];
        int h = jt >> 2;
        el0[h] += v0 * alsh[col] + v1 * alsh[col + 1];
        el1[h] += v2 * alsh[col] + v3 * alsh[col + 1];
        if (rowa < NN) { float2 p = make_float2(v0, v1); *(float2*)&hsout[(size_t)rowa * 128 + col] = p; }
        if (rowb < NN) { float2 p = make_float2(v2, v3); *(float2*)&hsout[(size_t)rowb * 128 + col] = p; }
    }
#pragma unroll
    for (int h = 0; h < 4; h++) {
        el0[h] += __shfl_xor_sync(0xffffffffu, el0[h], 1);
        el0[h] += __shfl_xor_sync(0xffffffffu, el0[h], 2);
        el1[h] += __shfl_xor_sync(0xffffffffu, el1[h], 1);
        el1[h] += __shfl_xor_sync(0xffffffffu, el1[h], 2);
    }
    if (tig == 0) {
        if (rowa < NN) *(float4*)&g_el[((size_t)r * NN + rowa) * 4] = make_float4(el0[0], el0[1], el0[2], el0[3]);
        if (rowb < NN) *(float4*)&g_el[((size_t)r * NN + rowb) * 4] = make_float4(el1[0], el1[1], el1[2], el1[3]);
    }
}

// ---------------- CSR build ----------------
__global__ void k_hist(const int* __restrict__ dst_idx) {
    int r = blockIdx.y;
    int e = blockIdx.x * blockDim.x + threadIdx.x;
    if (e >= EE) return;
    atomicAdd(&g_deg[r * NN + dst_idx[r * EE + e]], 1);
}

__global__ void k_scan1() {
    __shared__ int wsum[32];
    int i = blockIdx.x * 1024 + threadIdx.x;
    int lane = threadIdx.x & 31, wid = threadIdx.x >> 5;
    int v = (i < NNR) ? g_deg[i] : 0;
    int x = v;
#pragma unroll
    for (int o = 1; o < 32; o <<= 1) {
        int y = __shfl_up_sync(0xffffffffu, x, o);
        if (lane >= o) x += y;
    }
    if (lane == 31) wsum[wid] = x;
    __syncthreads();
    if (wid == 0) {
        int s = wsum[lane];
        int t2 = s;
#pragma unroll
        for (int o = 1; o < 32; o <<= 1) {
            int y = __shfl_up_sync(0xffffffffu, t2, o);
            if (lane >= o) t2 += y;
        }
        wsum[lane] = t2 - s;
        if (lane == 31) g_bsum[blockIdx.x] = t2;
    }
    __syncthreads();
    if (i < NNR) g_off[i] = x - v + wsum[wid];
}

__global__ void k_scan2(int nblocks) {
    __shared__ int wsum[32];
    int i = threadIdx.x;
    int lane = i & 31, wid = i >> 5;
    int v = (i < nblocks) ? g_bsum[i] : 0;
    int x = v;
#pragma unroll
    for (int o = 1; o < 32; o <<= 1) {
        int y = __shfl_up_sync(0xffffffffu, x, o);
        if (lane >= o) x += y;
    }
    if (lane == 31) wsum[wid] = x;
    __syncthreads();
    if (wid == 0) {
        int s = wsum[lane];
        int t2 = s;
#pragma unroll
        for (int o = 1; o < 32; o <<= 1) {
            int y = __shfl_up_sync(0xffffffffu, t2, o);
            if (lane >= o) t2 += y;
        }
        wsum[lane] = t2 - s;
    }
    __syncthreads();
    if (i < nblocks) g_boff[i] = x - v + wsum[wid];
}

__global__ void k_scan3() {
    int i = blockIdx.x * 1024 + threadIdx.x;
    if (i < NNR) g_off[i] += g_boff[blockIdx.x];
}

__global__ void k_scatter(const int* __restrict__ src_idx, const int* __restrict__ dst_idx) {
    int r = blockIdx.y;
    int e = blockIdx.x * blockDim.x + threadIdx.x;
    if (e >= EE) return;
    int idx = r * NN + dst_idx[r * EE + e];
    int pos = g_off[idx] + atomicAdd(&g_cur[idx], 1);
    g_csr[pos] = src_idx[r * EE + e];
}

// ---------------- fused: edge softmax + aggregate + bias + ELU ----------------
// one warp per (r, n); chunked-by-4 prefetch for MLP
__global__ __launch_bounds__(256) void k_agg(const float* __restrict__ bias_g) {
    int warp = (blockIdx.x * blockDim.x + threadIdx.x) >> 5;
    if (warp >= NNR) return;
    int lane = threadIdx.x & 31;
    int r = warp / NN;
    float4 er4 = *(const float4*)&g_er[warp * 4];
    int start = g_off[warp];
    int deg = g_deg[warp];
    const float* hsbase = g_hs + (size_t)r * NN * 128;
    const float* elbase = g_el + (size_t)r * NN * 4;
    float ss[4] = {0.f, 0.f, 0.f, 0.f};
    float ac[4] = {0.f, 0.f, 0.f, 0.f};
    int j = 0;
    for (; j + 4 <= deg; j += 4) {
        int s0 = __ldg(&g_csr[start + j + 0]);
        int s1 = __ldg(&g_csr[start + j + 1]);
        int s2 = __ldg(&g_csr[start + j + 2]);
        int s3 = __ldg(&g_csr[start + j + 3]);
        float4 e0 = __ldg((const float4*)&elbase[(size_t)s0 * 4]);
        float4 e1 = __ldg((const float4*)&elbase[(size_t)s1 * 4]);
        float4 e2 = __ldg((const float4*)&elbase[(size_t)s2 * 4]);
        float4 e3 = __ldg((const float4*)&elbase[(size_t)s3 * 4]);
        const float* h0 = hsbase + (size_t)s0 * 128 + lane;
        const float* h1 = hsbase + (size_t)s1 * 128 + lane;
        const float* h2 = hsbase + (size_t)s2 * 128 + lane;
        const float* h3 = hsbase + (size_t)s3 * 128 + lane;
        float h00 = __ldg(h0), h01 = __ldg(h0 + 32), h02 = __ldg(h0 + 64), h03 = __ldg(h0 + 96);
        float h10 = __ldg(h1), h11 = __ldg(h1 + 32), h12 = __ldg(h1 + 64), h13 = __ldg(h1 + 96);
        float h20 = __ldg(h2), h21 = __ldg(h2 + 32), h22 = __ldg(h2 + 64), h23 = __ldg(h2 + 96);
        float h30 = __ldg(h3), h31 = __ldg(h3 + 32), h32 = __ldg(h3 + 64), h33 = __ldg(h3 + 96);
#define EDGE(EV, HA, HB, HC, HD2)                                              \
        {                                                                      \
            float q0 = EV.x + er4.x; q0 = q0 > 0.f ? q0 : 0.2f * q0;           \
            float q1 = EV.y + er4.y; q1 = q1 > 0.f ? q1 : 0.2f * q1;           \
            float q2 = EV.z + er4.z; q2 = q2 > 0.f ? q2 : 0.2f * q2;           \
            float q3 = EV.w + er4.w; q3 = q3 > 0.f ? q3 : 0.2f * q3;           \
            float x0 = __expf(q0), x1 = __expf(q1), x2 = __expf(q2), x3 = __expf(q3); \
            ss[0] += x0; ss[1] += x1; ss[2] += x2; ss[3] += x3;                \
            ac[0] += x0 * HA; ac[1] += x1 * HB; ac[2] += x2 * HC; ac[3] += x3 * HD2; \
        }
        EDGE(e0, h00, h01, h02, h03)
        EDGE(e1, h10, h11, h12, h13)
        EDGE(e2, h20, h21, h22, h23)
        EDGE(e3, h30, h31, h32, h33)
    }
    for (; j < deg; j++) {
        int s = __ldg(&g_csr[start + j]);
        float4 ev = __ldg((const float4*)&elbase[(size_t)s * 4]);
        const float* hp = hsbase + (size_t)s * 128 + lane;
        float ha = __ldg(hp), hb = __ldg(hp + 32), hc = __ldg(hp + 64), hd = __ldg(hp + 96);
        EDGE(ev, ha, hb, hc, hd)
    }
#undef EDGE
    float i0 = 1.f / (ss[0] + 1e-9f);
    float i1 = 1.f / (ss[1] + 1e-9f);
    float i2 = 1.f / (ss[2] + 1e-9f);
    float i3 = 1.f / (ss[3] + 1e-9f);
    const float* bg = bias_g + r * 128 + lane;
    float v0 = ac[0] * i0 + bg[0];
    float v1 = ac[1] * i1 + bg[32];
    float v2 = ac[2] * i2 + bg[64];
    float v3 = ac[3] * i3 + bg[96];
    v0 = v0 > 0.f ? v0 : expm1f(v0);
    v1 = v1 > 0.f ? v1 : expm1f(v1);
    v2 = v2 > 0.f ? v2 : expm1f(v2);
    v3 = v3 > 0.f ? v3 : expm1f(v3);
    float* zp = g_rst + (size_t)warp * 128 + lane;
    zp[0] = v0; zp[32] = v1; zp[64] = v2; zp[96] = v3;
}

// ---------------- semantic attention GEMM on tensor cores ----------------
__global__ __launch_bounds__(128) void k_sem_tc(const float* __restrict__ b1,
                                                const float* __restrict__ W2) {
    extern __shared__ float sm[];
    float* Xs = sm;                               // 64 x 132
    unsigned* Wp = (unsigned*)(sm + 64 * 132);    // 16384
    float* b1sh = sm + 64 * 132 + 16384;          // 128
    float* w2sh = b1sh + 128;                     // 128
    float* bins = w2sh + 128;                     // 4
    int row0 = blockIdx.x * 64;
    int t = threadIdx.x;

    const uint4* Wsrc = (const uint4*)g_W1p;
    uint4* Wd = (uint4*)Wp;
    for (int i = t; i < 4096; i += 128) Wd[i] = Wsrc[i];
    b1sh[t] = b1[t];
    w2sh[t] = W2[t];
    if (t < 4) bins[t] = 0.f;
    for (int i = t; i < 2048; i += 128) {
        int rr = i >> 5, c4 = i & 31;
        float4 v = make_float4(0.f, 0.f, 0.f, 0.f);
        if (row0 + rr < NNR) v = *(const float4*)&g_rst[(size_t)(row0 + rr) * 128 + c4 * 4];
        *(float4*)&Xs[rr * 132 + c4 * 4] = v;
    }
    __syncthreads();

    int warp = t >> 5, lane = t & 31, g = lane >> 2, tig = lane & 3;
    int wr = warp * 16;
    float c[16][4];
#pragma unroll
    for (int j = 0; j < 16; j++)
        for (int q = 0; q < 4; q++) c[j][q] = 0.f;

#pragma unroll
    for (int s = 0; s < 16; s++) {
        int k0 = s * 8;
        unsigned a0 = __float_as_uint(Xs[(wr + g) * 132 + k0 + tig]);
        unsigned a1 = __float_as_uint(Xs[(wr + g + 8) * 132 + k0 + tig]);
        unsigned a2 = __float_as_uint(Xs[(wr + g) * 132 + k0 + tig + 4]);
        unsigned a3 = __float_as_uint(Xs[(wr + g + 8) * 132 + k0 + tig + 4]);
#pragma unroll
        for (int jt = 0; jt < 16; jt++) {
            uint2 b = *(const uint2*)&Wp[((s * 16 + jt) * 32 + lane) * 2];
            mma_tf32(c[jt], a0, a1, a2, a3, b.x, b.y);
        }
    }

    int rowa = row0 + wr + g;
    int rowb = rowa + 8;
    float s0 = 0.f, s1 = 0.f;
#pragma unroll
    for (int jt = 0; jt < 16; jt++) {
        int col = jt * 8 + tig * 2;
        s0 += w2sh[col] * tanhf(c[jt][0] + b1sh[col]) + w2sh[col + 1] * tanhf(c[jt][1] + b1sh[col + 1]);
        s1 += w2sh[col] * tanhf(c[jt][2] + b1sh[col]) + w2sh[col + 1] * tanhf(c[jt][3] + b1sh[col + 1]);
    }
    if (rowa < NNR) atomicAdd(&bins[rowa / NN], s0);
    if (rowb < NNR) atomicAdd(&bins[rowb / NN], s1);
    __syncthreads();
    if (t < RR) atomicAdd(&g_wsum[t], bins[t]);
}

// ---------------- softmax over relations ----------------
__global__ void k_soft(float* __restrict__ out, int out_size) {
    if (threadIdx.x == 0) {
        float w[RR];
        float m = -1e30f;
        for (int r = 0; r < RR; r++) { w[r] = g_wsum[r] / (float)NN; m = fmaxf(m, w[r]); }
        float s = 0.f;
        for (int r = 0; r < RR; r++) { w[r] = expf(w[r] - m); s += w[r]; }
        for (int r = 0; r < RR; r++) {
            float a = w[r] / s;
            g_aw[r] = a;
            out[out_size - RR + r] = a;
        }
    }
}

// ---------------- final weighted combination ----------------
__global__ void k_out(float* __restrict__ out) {
    int t = blockIdx.x * blockDim.x + threadIdx.x;
    if (t >= NN * 32) return;
    float a0 = g_aw[0], a1 = g_aw[1], a2 = g_aw[2];
    const float4* z0 = (const float4*)g_rst + t;
    const float4* z1 = z0 + (size_t)NN * 32;
    const float4* z2 = z1 + (size_t)NN * 32;
    float4 x = *z0, y = *z1, z = *z2;
    float4 o;
    o.x = a0 * x.x + a1 * y.x + a2 * z.x;
    o.y = a0 * x.y + a1 * y.y + a2 * z.y;
    o.z = a0 * x.z + a1 * y.z + a2 * z.z;
    o.w = a0 * x.w + a1 * y.w + a2 * z.w;
    ((float4*)out)[t] = o;
}

// ---------------- launch ----------------
extern "C" void kernel_launch(void* const* d_in, const int* in_sizes, int n_in,
                              void* d_out, int out_size) {
    const float* dst_feat  = (const float*)d_in[0];
    const float* src_feats = (const float*)d_in[1];
    const int*   src_idx   = (const int*)d_in[2];
    const int*   dst_idx   = (const int*)d_in[3];
    const float* Wt_dst    = (const float*)d_in[4];
    const float* bt_dst    = (const float*)d_in[5];
    const float* Wt_src    = (const float*)d_in[6];
    const float* bt_src    = (const float*)d_in[7];
    const float* Wg        = (const float*)d_in[8];
    const float* attn_l    = (const float*)d_in[9];
    const float* attn_r    = (const float*)d_in[10];
    const float* bias_g    = (const float*)d_in[11];
    const float* W1        = (const float*)d_in[12];
    const float* b1        = (const float*)d_in[13];
    const float* W2        = (const float*)d_in[14];
    float* out = (float*)d_out;

    void *pd, *pc, *pw;
    cudaGetSymbolAddress(&pd, g_deg);
    cudaGetSymbolAddress(&pc, g_cur);
    cudaGetSymbolAddress(&pw, g_wsum);
    cudaMemsetAsync(pd, 0, NNR * 4, 0);
    cudaMemsetAsync(pc, 0, NNR * 4, 0);
    cudaMemsetAsync(pw, 0, RR * 4, 0);

    const int SCAN_BLOCKS = (NNR + 1023) / 1024;  // 293
    const int SMEM_HS = (64 * 132 + 128 + 128) * 4 + 16384 * 4;
    const int SMEM_SEM = (64 * 132 + 128 + 128 + 4) * 4 + 16384 * 4;
    cudaFuncSetAttribute(k_hs_tc, cudaFuncAttributeMaxDynamicSharedMemorySize, SMEM_HS);
    cudaFuncSetAttribute(k_sem_tc, cudaFuncAttributeMaxDynamicSharedMemorySize, SMEM_SEM);

    k_combine_src<<<dim3(128, RR), 128>>>(Wt_src, bt_src, Wg);
    k_combine_dst<<<RR, 128>>>(Wt_dst, bt_dst, Wg, attn_r);
    k_permW1<<<128, 128>>>(W1);
    k_er<<<(NN + 127) / 128, 128>>>(dst_feat);
    k_hist<<<dim3((EE + 255) / 256, RR), 256>>>(dst_idx);
    k_scan1<<<SCAN_BLOCKS, 1024>>>();
    k_scan2<<<1, 1024>>>(SCAN_BLOCKS);
    k_scan3<<<SCAN_BLOCKS, 1024>>>();
    k_scatter<<<dim3((EE + 255) / 256, RR), 256>>>(src_idx, dst_idx);
    k_hs_tc<<<dim3((NN + 63) / 64, RR), 128, SMEM_HS>>>(src_feats, attn_l);
    k_agg<<<(NNR * 32 + 255) / 256, 256>>>(bias_g);
    k_sem_tc<<<(NNR + 63) / 64, 128, SMEM_SEM>>>(b1, W2);
    k_soft<<<1, 32>>>(out, out_size);
    k_out<<<(NN * 32 + 255) / 256, 256>>>(out);
}

// round 5
// speedup vs baseline: 1.9308x; 1.3146x over previous
#include <cuda_runtime.h>
#include <cstdint>

#define NN  100000
#define RR  3
#define EE  320000
#define HH  4
#define HD_ 128
#define NNR (RR * NN)

// ---------------- scratch (device globals; no allocs allowed) ----------------
__device__ float    g_hs  [(size_t)RR * NN * HD_];   // hs per relation  [r][n][128]
__device__ float    g_rst [(size_t)RR * NN * HD_];   // z_r
__device__ float    g_el  [NNR * HH];
__device__ float    g_er  [NNR * HH];
__device__ unsigned g_Ap  [RR * 128 * 128];          // Wt_src@Wg, tf32, fragment-permuted
__device__ unsigned g_W1p [128 * 128];               // W1, tf32, fragment-permuted
__device__ float    g_csrc[RR * 128];                // bt_src[r] @ Wg[r]
__device__ float    g_erw [RR * 128 * HH];
__device__ float    g_erb [RR * HH];
__device__ float    g_wsum[RR];
__device__ float    g_aw  [RR];
// CSR build
__device__ int      g_deg [NNR];
__device__ int      g_off [NNR];
__device__ int      g_cur [NNR];
__device__ int      g_bsum[512];
__device__ int      g_boff[512];
__device__ int      g_csr [RR * EE];

// fragment-permute position for B operand of m16n8k8.row.col (k x n element)
__host__ __device__ __forceinline__ int bpos(int k, int n) {
    int s = k >> 3, kl = k & 7, slot = kl >> 2, tig = kl & 3;
    int jt = n >> 3, g = n & 7;
    return ((s * 16 + jt) * 32 + g * 4 + tig) * 2 + slot;
}

__device__ __forceinline__ unsigned tf32r(float f) {
    unsigned v;
    asm("cvt.rna.tf32.f32 %0, %1;" : "=r"(v) : "f"(f));
    return v;
}

__device__ __forceinline__ void mma_tf32(float c[4], unsigned a0, unsigned a1,
                                         unsigned a2, unsigned a3,
                                         unsigned b0, unsigned b1) {
    asm volatile(
        "mma.sync.aligned.m16n8k8.row.col.f32.tf32.tf32.f32 "
        "{%0,%1,%2,%3},{%4,%5,%6,%7},{%8,%9},{%0,%1,%2,%3};"
        : "+f"(c[0]), "+f"(c[1]), "+f"(c[2]), "+f"(c[3])
        : "r"(a0), "r"(a1), "r"(a2), "r"(a3), "r"(b0), "r"(b1));
}

// ---------------- weight combination (writes permuted tf32 B) ----------------
__global__ void k_combine_src(const float* __restrict__ Wt_src,
                              const float* __restrict__ bt_src,
                              const float* __restrict__ Wg) {
    int r = blockIdx.y, f = blockIdx.x, j = threadIdx.x;
    __shared__ float wt[128];
    wt[j] = Wt_src[(r * 128 + f) * 128 + j];
    __syncthreads();
    const float* wg = Wg + r * 128 * 128;
    float acc = 0.f;
#pragma unroll 8
    for (int i = 0; i < 128; i++) acc += wt[i] * wg[i * 128 + j];
    g_Ap[r * 16384 + bpos(f, j)] = tf32r(acc);
    if (f == 0) {
        float c = 0.f;
        for (int i = 0; i < 128; i++) c += bt_src[r * 128 + i] * wg[i * 128 + j];
        g_csrc[r * 128 + j] = c;
    }
}

__global__ void k_permW1(const float* __restrict__ W1) {
    int k = blockIdx.x, j = threadIdx.x;
    g_W1p[bpos(k, j)] = tf32r(W1[k * 128 + j]);
}

__global__ void k_combine_dst(const float* __restrict__ Wt_dst,
                              const float* __restrict__ bt_dst,
                              const float* __restrict__ Wg,
                              const float* __restrict__ attn_r) {
    int r = blockIdx.x, t = threadIdx.x;  // 128 threads
    __shared__ float P[128][4];
    const float* wg = Wg + r * 128 * 128;
    const float* ar = attn_r + r * 128;
    for (int h = 0; h < 4; h++) {
        float s = 0.f;
        for (int d = 0; d < 32; d++) s += wg[t * 128 + h * 32 + d] * ar[h * 32 + d];
        P[t][h] = s;
    }
    __syncthreads();
    float s[4] = {0.f, 0.f, 0.f, 0.f};
    for (int i = 0; i < 128; i++) {
        float w = Wt_dst[t * 128 + i];
        for (int h = 0; h < 4; h++) s[h] += w * P[i][h];
    }
    for (int h = 0; h < 4; h++) g_erw[(r * 128 + t) * 4 + h] = s[h];
    if (t < 4) {
        float b = 0.f;
        for (int i = 0; i < 128; i++) b += bt_dst[i] * P[i][t];
        g_erb[r * 4 + t] = b;
    }
}

// er[r][n][h] = dst_feat[n] . er_w[r][:,h] + er_b[r][h]
__global__ __launch_bounds__(256) void k_er(const float* __restrict__ dst_feat) {
    __shared__ float sw[RR * 128 * 4];
    __shared__ float sb[RR * 4];
    int t = threadIdx.x;
    for (int idx = t; idx < RR * 128 * 4; idx += blockDim.x) sw[idx] = g_erw[idx];
    if (t < RR * 4) sb[t] = g_erb[t];
    __syncthreads();
    int n = blockIdx.x * blockDim.x + t;
    if (n >= NN) return;
    float acc[RR * 4];
    for (int q = 0; q < RR * 4; q++) acc[q] = sb[q];
    const float4* row = (const float4*)(dst_feat + (size_t)n * 128);
#pragma unroll 4
    for (int f4 = 0; f4 < 32; f4++) {
        float4 v = row[f4];
        const float c[4] = {v.x, v.y, v.z, v.w};
        for (int cc = 0; cc < 4; cc++) {
            int f = f4 * 4 + cc;
            for (int r = 0; r < RR; r++)
                for (int h = 0; h < 4; h++)
                    acc[r * 4 + h] += c[cc] * sw[(r * 128 + f) * 4 + h];
        }
    }
    for (int r = 0; r < RR; r++)
        for (int h = 0; h < 4; h++)
            g_er[(r * NN + n) * 4 + h] = acc[r * 4 + h];
}

// ---------------- hs GEMM on tensor cores, persistent weights, per relation ----
// block: 128 thr (4 warps); tile 64 rows x 128 cols; K=128; grid-stride over tiles
__global__ __launch_bounds__(128) void k_hs_tc(const float* __restrict__ src_feats,
                                               const float* __restrict__ attn_l, int r) {
    extern __shared__ float sm[];
    float* Xs = sm;                               // 64 x 132
    unsigned* Wp = (unsigned*)(sm + 64 * 132);    // 16384
    float* csh = sm + 64 * 132 + 16384;           // 128
    float* alsh = csh + 128;                      // 128
    int t = threadIdx.x;

    const uint4* Asrc = (const uint4*)(g_Ap + r * 16384);
    uint4* Wd = (uint4*)Wp;
    for (int i = t; i < 4096; i += 128) Wd[i] = Asrc[i];
    csh[t] = g_csrc[r * 128 + t];
    alsh[t] = attn_l[r * 128 + t];
    const float* X = src_feats + (size_t)r * NN * 128;
    float* hsout = g_hs + (size_t)r * NN * 128;

    int warp = t >> 5, lane = t & 31, g = lane >> 2, tig = lane & 3;
    int wr = warp * 16;
    const int NT = (NN + 63) / 64;

    for (int tile = blockIdx.x; tile < NT; tile += gridDim.x) {
        int row0 = tile * 64;
        __syncthreads();
        for (int i = t; i < 2048; i += 128) {
            int rr = i >> 5, c4 = i & 31;
            float4 v = make_float4(0.f, 0.f, 0.f, 0.f);
            if (row0 + rr < NN) v = *(const float4*)&X[(size_t)(row0 + rr) * 128 + c4 * 4];
            *(float4*)&Xs[rr * 132 + c4 * 4] = v;
        }
        __syncthreads();

        float c[16][4];
#pragma unroll
        for (int j = 0; j < 16; j++)
            for (int q = 0; q < 4; q++) c[j][q] = 0.f;

#pragma unroll
        for (int s = 0; s < 16; s++) {
            int k0 = s * 8;
            unsigned a0 = __float_as_uint(Xs[(wr + g) * 132 + k0 + tig]);
            unsigned a1 = __float_as_uint(Xs[(wr + g + 8) * 132 + k0 + tig]);
            unsigned a2 = __float_as_uint(Xs[(wr + g) * 132 + k0 + tig + 4]);
            unsigned a3 = __float_as_uint(Xs[(wr + g + 8) * 132 + k0 + tig + 4]);
#pragma unroll
            for (int jt = 0; jt < 16; jt++) {
                uint2 b = *(const uint2*)&Wp[((s * 16 + jt) * 32 + lane) * 2];
                mma_tf32(c[jt], a0, a1, a2, a3, b.x, b.y);
            }
        }

        int rowa = row0 + wr + g;
        int rowb = rowa + 8;
        float el0[4] = {0.f, 0.f, 0.f, 0.f};
        float el1[4] = {0.f, 0.f, 0.f, 0.f};
#pragma unroll
        for (int jt = 0; jt < 16; jt++) {
            int col = jt * 8 + tig * 2;
            float v0 = c[jt][0] + csh[col], v1 = c[jt][1] + csh[col + 1];
            float v2 = c[jt][2] + csh[col], v3 = c[jt][3] + csh[col + 1];
            int h = jt >> 2;
            el0[h] += v0 * alsh[col] + v1 * alsh[col + 1];
            el1[h] += v2 * alsh[col] + v3 * alsh[col + 1];
            if (rowa < NN) { float2 p = make_float2(v0, v1); *(float2*)&hsout[(size_t)rowa * 128 + col] = p; }
            if (rowb < NN) { float2 p = make_float2(v2, v3); *(float2*)&hsout[(size_t)rowb * 128 + col] = p; }
        }
#pragma unroll
        for (int h = 0; h < 4; h++) {
            el0[h] += __shfl_xor_sync(0xffffffffu, el0[h], 1);
            el0[h] += __shfl_xor_sync(0xffffffffu, el0[h], 2);
            el1[h] += __shfl_xor_sync(0xffffffffu, el1[h], 1);
            el1[h] += __shfl_xor_sync(0xffffffffu, el1[h], 2);
        }
        if (tig == 0) {
            if (rowa < NN) *(float4*)&g_el[((size_t)r * NN + rowa) * 4] = make_float4(el0[0], el0[1], el0[2], el0[3]);
            if (rowb < NN) *(float4*)&g_el[((size_t)r * NN + rowb) * 4] = make_float4(el1[0], el1[1], el1[2], el1[3]);
        }
    }
}

// ---------------- CSR build ----------------
__global__ void k_hist(const int* __restrict__ dst_idx) {
    int r = blockIdx.y;
    int e = blockIdx.x * blockDim.x + threadIdx.x;
    if (e >= EE) return;
    atomicAdd(&g_deg[r * NN + dst_idx[r * EE + e]], 1);
}

__global__ void k_scan1() {
    __shared__ int wsum[32];
    int i = blockIdx.x * 1024 + threadIdx.x;
    int lane = threadIdx.x & 31, wid = threadIdx.x >> 5;
    int v = (i < NNR) ? g_deg[i] : 0;
    int x = v;
#pragma unroll
    for (int o = 1; o < 32; o <<= 1) {
        int y = __shfl_up_sync(0xffffffffu, x, o);
        if (lane >= o) x += y;
    }
    if (lane == 31) wsum[wid] = x;
    __syncthreads();
    if (wid == 0) {
        int s = wsum[lane];
        int t2 = s;
#pragma unroll
        for (int o = 1; o < 32; o <<= 1) {
            int y = __shfl_up_sync(0xffffffffu, t2, o);
            if (lane >= o) t2 += y;
        }
        wsum[lane] = t2 - s;
        if (lane == 31) g_bsum[blockIdx.x] = t2;
    }
    __syncthreads();
    if (i < NNR) g_off[i] = x - v + wsum[wid];
}

__global__ void k_scan2(int nblocks) {
    __shared__ int wsum[32];
    int i = threadIdx.x;
    int lane = i & 31, wid = i >> 5;
    int v = (i < nblocks) ? g_bsum[i] : 0;
    int x = v;
#pragma unroll
    for (int o = 1; o < 32; o <<= 1) {
        int y = __shfl_up_sync(0xffffffffu, x, o);
        if (lane >= o) x += y;
    }
    if (lane == 31) wsum[wid] = x;
    __syncthreads();
    if (wid == 0) {
        int s = wsum[lane];
        int t2 = s;
#pragma unroll
        for (int o = 1; o < 32; o <<= 1) {
            int y = __shfl_up_sync(0xffffffffu, t2, o);
            if (lane >= o) t2 += y;
        }
        wsum[lane] = t2 - s;
    }
    __syncthreads();
    if (i < nblocks) g_boff[i] = x - v + wsum[wid];
}

__global__ void k_scan3() {
    int i = blockIdx.x * 1024 + threadIdx.x;
    if (i < NNR) g_off[i] += g_boff[blockIdx.x];
}

__global__ void k_scatter(const int* __restrict__ src_idx, const int* __restrict__ dst_idx) {
    int r = blockIdx.y;
    int e = blockIdx.x * blockDim.x + threadIdx.x;
    if (e >= EE) return;
    int idx = r * NN + dst_idx[r * EE + e];
    int pos = g_off[idx] + atomicAdd(&g_cur[idx], 1);
    g_csr[pos] = src_idx[r * EE + e];
}

// ---------------- fused: edge softmax + aggregate + bias + ELU (per relation) --
// one warp per node; chunked-by-4 prefetch for MLP; hs[r] is L2-hot
__global__ __launch_bounds__(256) void k_agg(const float* __restrict__ bias_g, int r) {
    int n = (blockIdx.x * blockDim.x + threadIdx.x) >> 5;
    if (n >= NN) return;
    int lane = threadIdx.x & 31;
    int node = r * NN + n;
    float4 er4 = *(const float4*)&g_er[node * 4];
    int start = g_off[node];
    int deg = g_deg[node];
    const float* hsbase = g_hs + (size_t)r * NN * 128;
    const float* elbase = g_el + (size_t)r * NN * 4;
    float ss[4] = {0.f, 0.f, 0.f, 0.f};
    float ac[4] = {0.f, 0.f, 0.f, 0.f};
    int j = 0;
    for (; j + 4 <= deg; j += 4) {
        int s0 = __ldg(&g_csr[start + j + 0]);
        int s1 = __ldg(&g_csr[start + j + 1]);
        int s2 = __ldg(&g_csr[start + j + 2]);
        int s3 = __ldg(&g_csr[start + j + 3]);
        float4 e0 = __ldg((const float4*)&elbase[(size_t)s0 * 4]);
        float4 e1 = __ldg((const float4*)&elbase[(size_t)s1 * 4]);
        float4 e2 = __ldg((const float4*)&elbase[(size_t)s2 * 4]);
        float4 e3 = __ldg((const float4*)&elbase[(size_t)s3 * 4]);
        const float* h0 = hsbase + (size_t)s0 * 128 + lane;
        const float* h1 = hsbase + (size_t)s1 * 128 + lane;
        const float* h2 = hsbase + (size_t)s2 * 128 + lane;
        const float* h3 = hsbase + (size_t)s3 * 128 + lane;
        float h00 = __ldg(h0), h01 = __ldg(h0 + 32), h02 = __ldg(h0 + 64), h03 = __ldg(h0 + 96);
        float h10 = __ldg(h1), h11 = __ldg(h1 + 32), h12 = __ldg(h1 + 64), h13 = __ldg(h1 + 96);
        float h20 = __ldg(h2), h21 = __ldg(h2 + 32), h22 = __ldg(h2 + 64), h23 = __ldg(h2 + 96);
        float h30 = __ldg(h3), h31 = __ldg(h3 + 32), h32 = __ldg(h3 + 64), h33 = __ldg(h3 + 96);
#define EDGE(EV, HA, HB, HC, HD2)                                              \
        {                                                                      \
            float q0 = EV.x + er4.x; q0 = q0 > 0.f ? q0 : 0.2f * q0;           \
            float q1 = EV.y + er4.y; q1 = q1 > 0.f ? q1 : 0.2f * q1;           \
            float q2 = EV.z + er4.z; q2 = q2 > 0.f ? q2 : 0.2f * q2;           \
            float q3 = EV.w + er4.w; q3 = q3 > 0.f ? q3 : 0.2f * q3;           \
            float x0 = __expf(q0), x1 = __expf(q1), x2 = __expf(q2), x3 = __expf(q3); \
            ss[0] += x0; ss[1] += x1; ss[2] += x2; ss[3] += x3;                \
            ac[0] += x0 * HA; ac[1] += x1 * HB; ac[2] += x2 * HC; ac[3] += x3 * HD2; \
        }
        EDGE(e0, h00, h01, h02, h03)
        EDGE(e1, h10, h11, h12, h13)
        EDGE(e2, h20, h21, h22, h23)
        EDGE(e3, h30, h31, h32, h33)
    }
    for (; j < deg; j++) {
        int s = __ldg(&g_csr[start + j]);
        float4 ev = __ldg((const float4*)&elbase[(size_t)s * 4]);
        const float* hp = hsbase + (size_t)s * 128 + lane;
        float ha = __ldg(hp), hb = __ldg(hp + 32), hc = __ldg(hp + 64), hd = __ldg(hp + 96);
        EDGE(ev, ha, hb, hc, hd)
    }
#undef EDGE
    float i0 = 1.f / (ss[0] + 1e-9f);
    float i1 = 1.f / (ss[1] + 1e-9f);
    float i2 = 1.f / (ss[2] + 1e-9f);
    float i3 = 1.f / (ss[3] + 1e-9f);
    const float* bg = bias_g + r * 128 + lane;
    float v0 = ac[0] * i0 + bg[0];
    float v1 = ac[1] * i1 + bg[32];
    float v2 = ac[2] * i2 + bg[64];
    float v3 = ac[3] * i3 + bg[96];
    v0 = v0 > 0.f ? v0 : expm1f(v0);
    v1 = v1 > 0.f ? v1 : expm1f(v1);
    v2 = v2 > 0.f ? v2 : expm1f(v2);
    v3 = v3 > 0.f ? v3 : expm1f(v3);
    float* zp = g_rst + (size_t)node * 128 + lane;
    zp[0] = v0; zp[32] = v1; zp[64] = v2; zp[96] = v3;
}

// ---------------- semantic attention GEMM on tensor cores, persistent --------
__global__ __launch_bounds__(128) void k_sem_tc(const float* __restrict__ b1,
                                                const float* __restrict__ W2) {
    extern __shared__ float sm[];
    float* Xs = sm;                               // 64 x 132
    unsigned* Wp = (unsigned*)(sm + 64 * 132);    // 16384
    float* b1sh = sm + 64 * 132 + 16384;          // 128
    float* w2sh = b1sh + 128;                     // 128
    float* bins = w2sh + 128;                     // 4
    int t = threadIdx.x;

    const uint4* Wsrc = (const uint4*)g_W1p;
    uint4* Wd = (uint4*)Wp;
    for (int i = t; i < 4096; i += 128) Wd[i] = Wsrc[i];
    b1sh[t] = b1[t];
    w2sh[t] = W2[t];
    if (t < 4) bins[t] = 0.f;

    int warp = t >> 5, lane = t & 31, g = lane >> 2, tig = lane & 3;
    int wr = warp * 16;
    const int NT = (NNR + 63) / 64;

    for (int tile = blockIdx.x; tile < NT; tile += gridDim.x) {
        int row0 = tile * 64;
        __syncthreads();
        for (int i = t; i < 2048; i += 128) {
            int rr = i >> 5, c4 = i & 31;
            float4 v = make_float4(0.f, 0.f, 0.f, 0.f);
            if (row0 + rr < NNR) v = *(const float4*)&g_rst[(size_t)(row0 + rr) * 128 + c4 * 4];
            *(float4*)&Xs[rr * 132 + c4 * 4] = v;
        }
        __syncthreads();

        float c[16][4];
#pragma unroll
        for (int j = 0; j < 16; j++)
            for (int q = 0; q < 4; q++) c[j][q] = 0.f;

#pragma unroll
        for (int s = 0; s < 16; s++) {
            int k0 = s * 8;
            unsigned a0 = __float_as_uint(Xs[(wr + g) * 132 + k0 + tig]);
            unsigned a1 = __float_as_uint(Xs[(wr + g + 8) * 132 + k0 + tig]);
            unsigned a2 = __float_as_uint(Xs[(wr + g) * 132 + k0 + tig + 4]);
            unsigned a3 = __float_as_uint(Xs[(wr + g + 8) * 132 + k0 + tig + 4]);
#pragma unroll
            for (int jt = 0; jt < 16; jt++) {
                uint2 b = *(const uint2*)&Wp[((s * 16 + jt) * 32 + lane) * 2];
                mma_tf32(c[jt], a0, a1, a2, a3, b.x, b.y);
            }
        }

        int rowa = row0 + wr + g;
        int rowb = rowa + 8;
        float s0 = 0.f, s1 = 0.f;
#pragma unroll
        for (int jt = 0; jt < 16; jt++) {
            int col = jt * 8 + tig * 2;
            s0 += w2sh[col] * tanhf(c[jt][0] + b1sh[col]) + w2sh[col + 1] * tanhf(c[jt][1] + b1sh[col + 1]);
            s1 += w2sh[col] * tanhf(c[jt][2] + b1sh[col]) + w2sh[col + 1] * tanhf(c[jt][3] + b1sh[col + 1]);
        }
        if (rowa < NNR) atomicAdd(&bins[rowa / NN], s0);
        if (rowb < NNR) atomicAdd(&bins[rowb / NN], s1);
    }
    __syncthreads();
    if (t < RR) atomicAdd(&g_wsum[t], bins[t]);
}

// ---------------- softmax over relations ----------------
__global__ void k_soft(float* __restrict__ out, int out_size) {
    if (threadIdx.x == 0) {
        float w[RR];
        float m = -1e30f;
        for (int r = 0; r < RR; r++) { w[r] = g_wsum[r] / (float)NN; m = fmaxf(m, w[r]); }
        float s = 0.f;
        for (int r = 0; r < RR; r++) { w[r] = expf(w[r] - m); s += w[r]; }
        for (int r = 0; r < RR; r++) {
            float a = w[r] / s;
            g_aw[r] = a;
            out[out_size - RR + r] = a;
        }
    }
}

// ---------------- final weighted combination ----------------
__global__ void k_out(float* __restrict__ out) {
    int t = blockIdx.x * blockDim.x + threadIdx.x;
    if (t >= NN * 32) return;
    float a0 = g_aw[0], a1 = g_aw[1], a2 = g_aw[2];
    const float4* z0 = (const float4*)g_rst + t;
    const float4* z1 = z0 + (size_t)NN * 32;
    const float4* z2 = z1 + (size_t)NN * 32;
    float4 x = *z0, y = *z1, z = *z2;
    float4 o;
    o.x = a0 * x.x + a1 * y.x + a2 * z.x;
    o.y = a0 * x.y + a1 * y.y + a2 * z.y;
    o.z = a0 * x.z + a1 * y.z + a2 * z.z;
    o.w = a0 * x.w + a1 * y.w + a2 * z.w;
    ((float4*)out)[t] = o;
}

// ---------------- launch ----------------
extern "C" void kernel_launch(void* const* d_in, const int* in_sizes, int n_in,
                              void* d_out, int out_size) {
    const float* dst_feat  = (const float*)d_in[0];
    const float* src_feats = (const float*)d_in[1];
    const int*   src_idx   = (const int*)d_in[2];
    const int*   dst_idx   = (const int*)d_in[3];
    const float* Wt_dst    = (const float*)d_in[4];
    const float* bt_dst    = (const float*)d_in[5];
    const float* Wt_src    = (const float*)d_in[6];
    const float* bt_src    = (const float*)d_in[7];
    const float* Wg        = (const float*)d_in[8];
    const float* attn_l    = (const float*)d_in[9];
    const float* attn_r    = (const float*)d_in[10];
    const float* bias_g    = (const float*)d_in[11];
    const float* W1        = (const float*)d_in[12];
    const float* b1        = (const float*)d_in[13];
    const float* W2        = (const float*)d_in[14];
    float* out = (float*)d_out;

    void *pd, *pc, *pw;
    cudaGetSymbolAddress(&pd, g_deg);
    cudaGetSymbolAddress(&pc, g_cur);
    cudaGetSymbolAddress(&pw, g_wsum);
    cudaMemsetAsync(pd, 0, NNR * 4, 0);
    cudaMemsetAsync(pc, 0, NNR * 4, 0);
    cudaMemsetAsync(pw, 0, RR * 4, 0);

    const int SCAN_BLOCKS = (NNR + 1023) / 1024;  // 293
    const int SMEM_HS = (64 * 132 + 128 + 128) * 4 + 16384 * 4;
    const int SMEM_SEM = (64 * 132 + 128 + 128 + 4) * 4 + 16384 * 4;
    cudaFuncSetAttribute(k_hs_tc, cudaFuncAttributeMaxDynamicSharedMemorySize, SMEM_HS);
    cudaFuncSetAttribute(k_sem_tc, cudaFuncAttributeMaxDynamicSharedMemorySize, SMEM_SEM);
    const int PBLK = 296;  // 2 blocks/SM x 148 SMs

    k_combine_src<<<dim3(128, RR), 128>>>(Wt_src, bt_src, Wg);
    k_combine_dst<<<RR, 128>>>(Wt_dst, bt_dst, Wg, attn_r);
    k_permW1<<<128, 128>>>(W1);
    k_er<<<(NN + 255) / 256, 256>>>(dst_feat);
    k_hist<<<dim3((EE + 255) / 256, RR), 256>>>(dst_idx);
    k_scan1<<<SCAN_BLOCKS, 1024>>>();
    k_scan2<<<1, 1024>>>(SCAN_BLOCKS);
    k_scan3<<<SCAN_BLOCKS, 1024>>>();
    k_scatter<<<dim3((EE + 255) / 256, RR), 256>>>(src_idx, dst_idx);
    // interleave per relation: hs[r] stays L2-resident for agg[r]'s gather
    for (int r = 0; r < RR; r++) {
        k_hs_tc<<<PBLK, 128, SMEM_HS>>>(src_feats, attn_l, r);
        k_agg<<<(NN * 32 + 255) / 256, 256>>>(bias_g, r);
    }
    k_sem_tc<<<PBLK, 128, SMEM_SEM>>>(b1, W2);
    k_soft<<<1, 32>>>(out, out_size);
    k_out<<<(NN * 32 + 255) / 256, 256>>>(out);
}